// round 5
// baseline (speedup 1.0000x reference)
#include <cuda_runtime.h>
#include <math.h>

#define EPS 1e-7f
#define ONE_M_EPS (1.0f - 1e-7f)

// Problem constants (fixed shapes from setup_inputs)
#define NSEQ 512
#define DIM 512
#define NH 8
#define HD 64

// Scratch (no allocation allowed; __device__ globals)
__device__ float g_scale[NSEQ];
__device__ float g_qkv[NSEQ * 3 * DIM];       // (N, 1536)
__device__ float g_qh[NH * NSEQ * HD];        // (H, N, 64)
__device__ float g_kh[NH * NSEQ * HD];
__device__ float g_q2[NH * NSEQ];
__device__ float g_k2[NH * NSEQ];
__device__ float g_attn[NSEQ * DIM];          // (N, 512): [n][h*64+d]

__device__ __forceinline__ float warp_sum(float v) {
#pragma unroll
    for (int s = 16; s; s >>= 1) v += __shfl_xor_sync(0xffffffffu, v, s);
    return v;
}
__device__ __forceinline__ float warp_max(float v) {
#pragma unroll
    for (int s = 16; s; s >>= 1) v = fmaxf(v, __shfl_xor_sync(0xffffffffu, v, s));
    return v;
}
__device__ __forceinline__ float softplusf(float x) {
    return (x > 20.f) ? x : log1pf(__expf(x));
}

// ---------------------------------------------------------------------------
// Kernel A: logmap0 row scale.  x_tan[n] = x_hyp[n] * g_scale[n]
// one warp per row; 8 warps/block, 64 blocks
// ---------------------------------------------------------------------------
__global__ void rowscale_kernel(const float* __restrict__ x,
                                const float* __restrict__ c_sphere) {
    int warp = threadIdx.x >> 5, lane = threadIdx.x & 31;
    int row = blockIdx.x * 8 + warp;
    const float4* xr = (const float4*)(x + row * DIM);
    float ss = 0.f;
#pragma unroll
    for (int q = 0; q < 4; q++) {
        float4 v = xr[lane + q * 32];
        ss += v.x * v.x + v.y * v.y + v.z * v.z + v.w * v.w;
    }
    ss = warp_sum(ss);
    if (lane == 0) {
        float yn = sqrtf(ss);
        float sc = fmaxf(sqrtf(c_sphere[0]), EPS);
        float s = 0.f;
        if (yn >= EPS)
            s = atanhf(fminf(yn, ONE_M_EPS)) / (sc * fmaxf(yn, EPS));
        g_scale[row] = s;
    }
}

// ---------------------------------------------------------------------------
// Tiled fp32 GEMM: C[M,N] = (scale ? diag(rowscale)*A : A) @ B + bias
// BM=BN=64, BK=16, 256 threads, 4x4 per thread. M,N mult of 64, K mult of 16.
// ---------------------------------------------------------------------------
template <bool HAS_SCALE>
__global__ void gemm_kernel(const float* __restrict__ A, const float* __restrict__ B,
                            const float* __restrict__ bias,
                            const float* __restrict__ rowscale,
                            float* __restrict__ C, int M, int N, int K) {
    __shared__ float As[16][65];
    __shared__ float Bs[16][64];
    int tid = threadIdx.x;
    int tx = tid & 15, ty = tid >> 4;
    int m0 = blockIdx.y * 64, n0 = blockIdx.x * 64;
    int aRow = tid >> 2, aCol = (tid & 3) * 4;
    int bRow = tid >> 4, bCol = (tid & 15) * 4;
    float acc[4][4] = {};
    float ascale = 1.f;
    if (HAS_SCALE) ascale = rowscale[m0 + aRow];

    for (int kb = 0; kb < K; kb += 16) {
        float4 a4 = *(const float4*)(A + (size_t)(m0 + aRow) * K + kb + aCol);
        if (HAS_SCALE) { a4.x *= ascale; a4.y *= ascale; a4.z *= ascale; a4.w *= ascale; }
        As[aCol + 0][aRow] = a4.x;
        As[aCol + 1][aRow] = a4.y;
        As[aCol + 2][aRow] = a4.z;
        As[aCol + 3][aRow] = a4.w;
        *(float4*)&Bs[bRow][bCol] =
            *(const float4*)(B + (size_t)(kb + bRow) * N + n0 + bCol);
        __syncthreads();
#pragma unroll
        for (int k = 0; k < 16; k++) {
            float a0 = As[k][ty * 4 + 0];
            float a1 = As[k][ty * 4 + 1];
            float a2 = As[k][ty * 4 + 2];
            float a3 = As[k][ty * 4 + 3];
            float4 b4 = *(float4*)&Bs[k][tx * 4];
            acc[0][0] += a0 * b4.x; acc[0][1] += a0 * b4.y; acc[0][2] += a0 * b4.z; acc[0][3] += a0 * b4.w;
            acc[1][0] += a1 * b4.x; acc[1][1] += a1 * b4.y; acc[1][2] += a1 * b4.z; acc[1][3] += a1 * b4.w;
            acc[2][0] += a2 * b4.x; acc[2][1] += a2 * b4.y; acc[2][2] += a2 * b4.z; acc[2][3] += a2 * b4.w;
            acc[3][0] += a3 * b4.x; acc[3][1] += a3 * b4.y; acc[3][2] += a3 * b4.z; acc[3][3] += a3 * b4.w;
        }
        __syncthreads();
    }
    float4 bv = *(const float4*)(bias + n0 + tx * 4);
#pragma unroll
    for (int i = 0; i < 4; i++) {
        float4 o;
        o.x = acc[i][0] + bv.x;
        o.y = acc[i][1] + bv.y;
        o.z = acc[i][2] + bv.z;
        o.w = acc[i][3] + bv.w;
        *(float4*)(C + (size_t)(m0 + ty * 4 + i) * N + n0 + tx * 4) = o;
    }
}

// ---------------------------------------------------------------------------
// Kernel C: RoPE + expmap0 + projection for q and k; also per-row x2.
// One warp per (h, n); lane l owns dims l and l+32 (RoPE pair is local).
// ---------------------------------------------------------------------------
__global__ void rope_expmap_kernel(const float* __restrict__ freqs,
                                   const float* __restrict__ c_logits) {
    int warp = threadIdx.x >> 5, lane = threadIdx.x & 31;
    int idx = blockIdx.x * 8 + warp;   // 0..4095
    int h = idx & 7, n = idx >> 3;
    float c = softplusf(c_logits[h]);
    float sc = fmaxf(sqrtf(c), EPS);
    float f = freqs[n * 32 + lane];
    float cs = cosf(f), sn = sinf(f);
    const float* base = g_qkv + (size_t)n * 1536 + h * 64;
#pragma unroll
    for (int w = 0; w < 2; w++) {   // w=0: q, w=1: k
        const float* src = base + w * DIM;
        float xr = src[lane], xi = src[lane + 32];
        float r0 = xr * cs - xi * sn;     // -> dim lane
        float r1 = xr * sn + xi * cs;     // -> dim lane+32
        float vn = sqrtf(warp_sum(r0 * r0 + r1 * r1));
        float mag = tanhf(sc * vn) / sc;
        float s = (vn < EPS) ? 0.f : mag / fmaxf(vn, EPS);
        if (mag >= 1.0f) s *= ONE_M_EPS / fmaxf(mag, EPS);  // _project
        float o0 = r0 * s, o1 = r1 * s;
        float x2 = warp_sum(o0 * o0 + o1 * o1);
        float* dst = (w == 0 ? g_qh : g_kh) + (size_t)(h * NSEQ + n) * HD;
        dst[lane] = o0;
        dst[lane + 32] = o1;
        if (lane == 0) (w == 0 ? g_q2 : g_k2)[h * NSEQ + n] = x2;
    }
}

// ---------------------------------------------------------------------------
// Kernel D: fused hyperbolic-distance attention (causal, online softmax).
// grid = (64, 8): blockIdx.y = head, block handles 8 consecutive queries
// (one warp per query). Key tiles of 32: lane = key.
// dist_ij collapses to f(q2_i, k2_j, dot_ij, c_h) — no (N,N,d) intermediate.
// ---------------------------------------------------------------------------
__global__ void attn_kernel(const float* __restrict__ c_logits,
                            const float* __restrict__ geo_scale) {
    __shared__ float ktT[64 * 33];   // transposed K tile, padded
    __shared__ float vt[32 * 64];    // V tile row-major
    __shared__ float k2s[32];
    int tid = threadIdx.x;
    int warp = tid >> 5, lane = tid & 31;
    int h = blockIdx.y;
    int qi = blockIdx.x * 8 + warp;

    float c = softplusf(c_logits[h]);
    float sc = fmaxf(sqrtf(c), EPS);
    float gs = geo_scale[h];
    float c2 = c * c;
    float neg_gs2sc = -gs * 2.0f / sc;

    const float* qrow = g_qh + (size_t)(h * NSEQ + qi) * HD;
    float q0 = qrow[lane], q1 = qrow[lane + 32];
    float q2v = g_q2[h * NSEQ + qi];
    float b = 1.f - c * q2v;

    float m = -INFINITY, l = 0.f, o0 = 0.f, o1 = 0.f;
    int kmax = blockIdx.x * 8 + 7;
    int ntiles = (kmax >> 5) + 1;

    for (int t = 0; t < ntiles; t++) {
        int j0 = t * 32;
        // stage K tile (transposed) and V tile
        for (int e = tid; e < 2048; e += 256) {
            int j = e >> 6, d = e & 63;
            ktT[d * 33 + j] = g_kh[(size_t)(h * NSEQ + j0 + j) * HD + d];
            vt[j * 64 + d] = g_qkv[(size_t)(j0 + j) * 1536 + 2 * DIM + h * 64 + d];
        }
        if (tid < 32) k2s[tid] = g_k2[h * NSEQ + j0 + tid];
        __syncthreads();

        if (qi >= j0) {
            // dot(q, k_j) for this lane's key j = j0+lane
            float dot = 0.f;
#pragma unroll
            for (int d = 0; d < 32; d++) {
                float qd = __shfl_sync(0xffffffffu, q0, d);
                dot += qd * ktT[d * 33 + lane];
            }
#pragma unroll
            for (int d = 0; d < 32; d++) {
                float qd = __shfl_sync(0xffffffffu, q1, d);
                dot += qd * ktT[(d + 32) * 33 + lane];
            }
            int j = j0 + lane;
            bool valid = (j <= qi);
            float k2 = k2s[lane];
            float xy = -dot;
            float t2 = 2.f * c * xy;
            float a = 1.f + t2 + c * k2;
            float den = 1.f + t2 + c2 * q2v * k2;
            float num2 = a * a * q2v + 2.f * a * b * xy + b * b * k2;
            num2 = fmaxf(num2, 0.f);
            float nrm = sqrtf(num2) / fmaxf(den, EPS);
            if (nrm >= 1.0f) nrm = ONE_M_EPS;               // _project
            float arg = fminf(sc * nrm, ONE_M_EPS);
            float at = 0.5f * __logf(__fdividef(1.f + arg, 1.f - arg));
            float score = valid ? (neg_gs2sc * at) : -INFINITY;

            // online softmax
            float tmax = warp_max(score);
            float m_new = fmaxf(m, tmax);
            float corr = (m > -1e37f) ? __expf(m - m_new) : 0.f;
            float p = valid ? __expf(score - m_new) : 0.f;
            float psum = warp_sum(p);
            l = l * corr + psum;
            o0 *= corr; o1 *= corr;
            m = m_new;
#pragma unroll
            for (int jj = 0; jj < 32; jj++) {
                float pj = __shfl_sync(0xffffffffu, p, jj);
                o0 += pj * vt[jj * 64 + lane];
                o1 += pj * vt[jj * 64 + lane + 32];
            }
        }
        __syncthreads();
    }
    float inv_l = __frcp_rn(l);
    g_attn[(size_t)qi * DIM + h * 64 + lane] = o0 * inv_l;
    g_attn[(size_t)qi * DIM + h * 64 + lane + 32] = o1 * inv_l;
}

// ---------------------------------------------------------------------------
extern "C" void kernel_launch(void* const* d_in, const int* in_sizes, int n_in,
                              void* d_out, int out_size) {
    const float* x_hyp    = (const float*)d_in[0];
    const float* freqs    = (const float*)d_in[1];
    const float* c_sphere = (const float*)d_in[2];
    const float* w_qkv    = (const float*)d_in[3];
    const float* b_qkv    = (const float*)d_in[4];
    const float* w_out    = (const float*)d_in[5];
    const float* b_out    = (const float*)d_in[6];
    const float* c_logits = (const float*)d_in[7];
    const float* geo      = (const float*)d_in[8];
    float* out = (float*)d_out;

    void *p_qkv = nullptr, *p_attn = nullptr, *p_scale = nullptr;
    cudaGetSymbolAddress(&p_qkv, g_qkv);
    cudaGetSymbolAddress(&p_attn, g_attn);
    cudaGetSymbolAddress(&p_scale, g_scale);

    // 1. logmap0 row scales
    rowscale_kernel<<<64, 256>>>(x_hyp, c_sphere);
    // 2. qkv = (x_hyp * scale) @ w_qkv + b_qkv   (M=512, N=1536, K=512)
    gemm_kernel<true><<<dim3(24, 8), 256>>>(x_hyp, w_qkv, b_qkv,
                                            (const float*)p_scale,
                                            (float*)p_qkv, NSEQ, 3 * DIM, DIM);
    // 3. RoPE + expmap0 + norms
    rope_expmap_kernel<<<512, 256>>>(freqs, c_logits);
    // 4. fused hyperbolic attention
    attn_kernel<<<dim3(64, 8), 256>>>(c_logits, geo);
    // 5. out = attn_out @ w_out + b_out   (M=N=K=512)
    gemm_kernel<false><<<dim3(8, 8), 256>>>((const float*)p_attn, w_out, b_out,
                                            nullptr, out, NSEQ, DIM, DIM);
}

// round 9
// speedup vs baseline: 1.1581x; 1.1581x over previous
#include <cuda_runtime.h>
#include <math.h>

#define EPS 1e-7f
#define ONE_M_EPS (1.0f - 1e-7f)

// Problem constants (fixed shapes from setup_inputs)
#define NSEQ 512
#define DIM 512
#define NH 8
#define HD 64

// Scratch (no allocation allowed; __device__ globals)
__device__ float g_scale[NSEQ];
__device__ float g_qkv[NSEQ * 3 * DIM];       // (N, 1536)
__device__ float g_qh[NH * NSEQ * HD];        // (H, N, 64)
__device__ float g_kh[NH * NSEQ * HD];
__device__ float g_q2[NH * NSEQ];
__device__ float g_k2[NH * NSEQ];
__device__ float g_attn[NSEQ * DIM];          // (N, 512): [n][h*64+d]

__device__ __forceinline__ float warp_sum(float v) {
#pragma unroll
    for (int s = 16; s; s >>= 1) v += __shfl_xor_sync(0xffffffffu, v, s);
    return v;
}
__device__ __forceinline__ float softplusf(float x) {
    return (x > 20.f) ? x : log1pf(__expf(x));
}

// ---------------------------------------------------------------------------
// Kernel A: logmap0 row scale.
// ---------------------------------------------------------------------------
__global__ void rowscale_kernel(const float* __restrict__ x,
                                const float* __restrict__ c_sphere) {
    int warp = threadIdx.x >> 5, lane = threadIdx.x & 31;
    int row = blockIdx.x * 8 + warp;
    const float4* xr = (const float4*)(x + row * DIM);
    float ss = 0.f;
#pragma unroll
    for (int q = 0; q < 4; q++) {
        float4 v = xr[lane + q * 32];
        ss += v.x * v.x + v.y * v.y + v.z * v.z + v.w * v.w;
    }
    ss = warp_sum(ss);
    if (lane == 0) {
        float yn = sqrtf(ss);
        float sc = fmaxf(sqrtf(c_sphere[0]), EPS);
        float s = 0.f;
        if (yn >= EPS)
            s = atanhf(fminf(yn, ONE_M_EPS)) / (sc * fmaxf(yn, EPS));
        g_scale[row] = s;
    }
}

// ---------------------------------------------------------------------------
// Tiled fp32 GEMM: C[M,N] = (scale ? diag(rowscale)*A : A) @ B + bias
// BM=BN=64, BK=16, 256 threads, 4x4 per thread.
// As padded to 68 floats/row (16B-aligned rows) so the A micro-tile read is
// a single LDS.128 instead of 4x LDS.32.
// ---------------------------------------------------------------------------
template <bool HAS_SCALE>
__global__ void gemm_kernel(const float* __restrict__ A, const float* __restrict__ B,
                            const float* __restrict__ bias,
                            const float* __restrict__ rowscale,
                            float* __restrict__ C, int M, int N, int K) {
    __shared__ float As[16][68];
    __shared__ float Bs[16][64];
    int tid = threadIdx.x;
    int tx = tid & 15, ty = tid >> 4;
    int m0 = blockIdx.y * 64, n0 = blockIdx.x * 64;
    int aRow = tid >> 2, aCol = (tid & 3) * 4;
    int bRow = tid >> 4, bCol = (tid & 15) * 4;
    float acc[4][4] = {};
    float ascale = 1.f;
    if (HAS_SCALE) ascale = rowscale[m0 + aRow];

    for (int kb = 0; kb < K; kb += 16) {
        float4 a4 = *(const float4*)(A + (size_t)(m0 + aRow) * K + kb + aCol);
        if (HAS_SCALE) { a4.x *= ascale; a4.y *= ascale; a4.z *= ascale; a4.w *= ascale; }
        As[aCol + 0][aRow] = a4.x;
        As[aCol + 1][aRow] = a4.y;
        As[aCol + 2][aRow] = a4.z;
        As[aCol + 3][aRow] = a4.w;
        *(float4*)&Bs[bRow][bCol] =
            *(const float4*)(B + (size_t)(kb + bRow) * N + n0 + bCol);
        __syncthreads();
#pragma unroll
        for (int k = 0; k < 16; k++) {
            float4 av = *(float4*)&As[k][ty * 4];
            float4 b4 = *(float4*)&Bs[k][tx * 4];
            acc[0][0] += av.x * b4.x; acc[0][1] += av.x * b4.y; acc[0][2] += av.x * b4.z; acc[0][3] += av.x * b4.w;
            acc[1][0] += av.y * b4.x; acc[1][1] += av.y * b4.y; acc[1][2] += av.y * b4.z; acc[1][3] += av.y * b4.w;
            acc[2][0] += av.z * b4.x; acc[2][1] += av.z * b4.y; acc[2][2] += av.z * b4.z; acc[2][3] += av.z * b4.w;
            acc[3][0] += av.w * b4.x; acc[3][1] += av.w * b4.y; acc[3][2] += av.w * b4.z; acc[3][3] += av.w * b4.w;
        }
        __syncthreads();
    }
    float4 bv = *(const float4*)(bias + n0 + tx * 4);
#pragma unroll
    for (int i = 0; i < 4; i++) {
        float4 o;
        o.x = acc[i][0] + bv.x;
        o.y = acc[i][1] + bv.y;
        o.z = acc[i][2] + bv.z;
        o.w = acc[i][3] + bv.w;
        *(float4*)(C + (size_t)(m0 + ty * 4 + i) * N + n0 + tx * 4) = o;
    }
}

// ---------------------------------------------------------------------------
// Kernel C: RoPE + expmap0 + norms (unchanged)
// ---------------------------------------------------------------------------
__global__ void rope_expmap_kernel(const float* __restrict__ freqs,
                                   const float* __restrict__ c_logits) {
    int warp = threadIdx.x >> 5, lane = threadIdx.x & 31;
    int idx = blockIdx.x * 8 + warp;   // 0..4095
    int h = idx & 7, n = idx >> 3;
    float c = softplusf(c_logits[h]);
    float sc = fmaxf(sqrtf(c), EPS);
    float f = freqs[n * 32 + lane];
    float cs = cosf(f), sn = sinf(f);
    const float* base = g_qkv + (size_t)n * 1536 + h * 64;
#pragma unroll
    for (int w = 0; w < 2; w++) {   // w=0: q, w=1: k
        const float* src = base + w * DIM;
        float xr = src[lane], xi = src[lane + 32];
        float r0 = xr * cs - xi * sn;
        float r1 = xr * sn + xi * cs;
        float vn = sqrtf(warp_sum(r0 * r0 + r1 * r1));
        float mag = tanhf(sc * vn) / sc;
        float s = (vn < EPS) ? 0.f : mag / fmaxf(vn, EPS);
        if (mag >= 1.0f) s *= ONE_M_EPS / fmaxf(mag, EPS);  // _project
        float o0 = r0 * s, o1 = r1 * s;
        float x2 = warp_sum(o0 * o0 + o1 * o1);
        float* dst = (w == 0 ? g_qh : g_kh) + (size_t)(h * NSEQ + n) * HD;
        dst[lane] = o0;
        dst[lane + 32] = o1;
        if (lane == 0) (w == 0 ? g_q2 : g_k2)[h * NSEQ + n] = x2;
    }
}

// ---------------------------------------------------------------------------
// Kernel D v2: GEMM-shaped fused hyperbolic attention.
// grid (16, 8): blockIdx.y = head, block = 32 queries. 256 threads.
// ---------------------------------------------------------------------------
__device__ __forceinline__ float hyp_score(float dot, float q2, float k2, float b,
                                           float c, float c2, float sc,
                                           float neg_gs2sc) {
    float xy = -dot;
    float t2 = 2.f * c * xy;
    float a = 1.f + t2 + c * k2;
    float den = 1.f + t2 + c2 * q2 * k2;
    float num2 = fmaxf(a * a * q2 + 2.f * a * b * xy + b * b * k2, 0.f);
    float nrm = sqrtf(num2) / fmaxf(den, EPS);
    if (nrm >= 1.f) nrm = ONE_M_EPS;                    // _project
    float arg = fminf(sc * nrm, ONE_M_EPS);
    float at = 0.5f * __logf(__fdividef(1.f + arg, 1.f - arg));
    return neg_gs2sc * at;
}

__global__ __launch_bounds__(256) void attn_kernel(const float* __restrict__ c_logits,
                                                   const float* __restrict__ geo_scale) {
    __shared__ float Qs[32][68];
    __shared__ float Ks[32][68];
    __shared__ float Vs[32][68];
    __shared__ float Ss[32][36];
    __shared__ float q2s[32], k2s[32], bs[32], ms[32], ls[32], cr[32];

    int tid = threadIdx.x;
    int lane = tid & 31, warp = tid >> 5;
    int h = blockIdx.y, qb = blockIdx.x;

    float c = softplusf(c_logits[h]);
    float sc = fmaxf(sqrtf(c), EPS);
    float gs = geo_scale[h];
    float c2 = c * c;
    float neg_gs2sc = -gs * 2.0f / sc;

    // ---- prologue: Q tile + row stats ----
    {
        const float* qbase = g_qh + ((size_t)h * NSEQ + qb * 32) * HD;
#pragma unroll
        for (int e = tid; e < 512; e += 256) {       // float4 units
            int row = e >> 4, dc = e & 15;
            *(float4*)&Qs[row][dc * 4] = *(const float4*)(qbase + row * 64 + dc * 4);
        }
        if (tid < 32) {
            float q2 = g_q2[h * NSEQ + qb * 32 + tid];
            q2s[tid] = q2;
            bs[tid] = 1.f - c * q2;
            ms[tid] = -INFINITY;
            ls[tid] = 0.f;
        }
    }

    // PV ownership: row pr, dim clusters pc*4.. and 32+pc*4..
    int pr = tid >> 3, pc = tid & 7;
    float4 oA = {0.f, 0.f, 0.f, 0.f}, oB = {0.f, 0.f, 0.f, 0.f};

    // score ownership: rows ty, ty+16; cols tx, tx+16
    int ty = tid >> 4, tx = tid & 15;
    // softmax ownership: row sr (4 per warp), 8 lanes each
    int sr = (warp << 2) + (lane >> 3), part = lane & 7;

    for (int t = 0; t <= qb; t++) {
        // ---- stage K, V, k2 ----
        const float* kbase = g_kh + ((size_t)h * NSEQ + t * 32) * HD;
        const float* vbase = g_qkv + (size_t)(t * 32) * 1536 + 2 * DIM + h * 64;
#pragma unroll
        for (int e = tid; e < 512; e += 256) {
            int row = e >> 4, dc = e & 15;
            *(float4*)&Ks[row][dc * 4] = *(const float4*)(kbase + row * 64 + dc * 4);
            *(float4*)&Vs[row][dc * 4] = *(const float4*)(vbase + (size_t)row * 1536 + dc * 4);
        }
        if (tid < 32) k2s[tid] = g_k2[h * NSEQ + t * 32 + tid];
        __syncthreads();

        // ---- score phase: 2x2 dots over 64 dims ----
        float d00 = 0.f, d01 = 0.f, d10 = 0.f, d11 = 0.f;
#pragma unroll
        for (int dc = 0; dc < 16; dc++) {
            float4 qa = *(float4*)&Qs[ty][dc * 4];
            float4 qc = *(float4*)&Qs[ty + 16][dc * 4];
            float4 ka = *(float4*)&Ks[tx][dc * 4];
            float4 kc = *(float4*)&Ks[tx + 16][dc * 4];
            d00 += qa.x * ka.x + qa.y * ka.y + qa.z * ka.z + qa.w * ka.w;
            d01 += qa.x * kc.x + qa.y * kc.y + qa.z * kc.z + qa.w * kc.w;
            d10 += qc.x * ka.x + qc.y * ka.y + qc.z * ka.z + qc.w * ka.w;
            d11 += qc.x * kc.x + qc.y * kc.y + qc.z * kc.z + qc.w * kc.w;
        }
        {
            int qg0 = qb * 32 + ty, qg1 = qg0 + 16;
            int jg0 = t * 32 + tx, jg1 = jg0 + 16;
            float q2a = q2s[ty], q2b = q2s[ty + 16];
            float ba = bs[ty], bb = bs[ty + 16];
            float k2a = k2s[tx], k2b = k2s[tx + 16];
            Ss[ty][tx]           = (jg0 <= qg0) ? hyp_score(d00, q2a, k2a, ba, c, c2, sc, neg_gs2sc) : -INFINITY;
            Ss[ty][tx + 16]      = (jg1 <= qg0) ? hyp_score(d01, q2a, k2b, ba, c, c2, sc, neg_gs2sc) : -INFINITY;
            Ss[ty + 16][tx]      = (jg0 <= qg1) ? hyp_score(d10, q2b, k2a, bb, c, c2, sc, neg_gs2sc) : -INFINITY;
            Ss[ty + 16][tx + 16] = (jg1 <= qg1) ? hyp_score(d11, q2b, k2b, bb, c, c2, sc, neg_gs2sc) : -INFINITY;
        }
        __syncthreads();

        // ---- online softmax: 8 lanes per row ----
        {
            float4 s4 = *(float4*)&Ss[sr][part * 4];
            float mx = fmaxf(fmaxf(s4.x, s4.y), fmaxf(s4.z, s4.w));
#pragma unroll
            for (int d = 1; d < 8; d <<= 1)
                mx = fmaxf(mx, __shfl_xor_sync(0xffffffffu, mx, d));
            float mold = ms[sr];
            float mnew = fmaxf(mold, mx);
            float4 p4;
            p4.x = __expf(s4.x - mnew);
            p4.y = __expf(s4.y - mnew);
            p4.z = __expf(s4.z - mnew);
            p4.w = __expf(s4.w - mnew);
            float ps = p4.x + p4.y + p4.z + p4.w;
#pragma unroll
            for (int d = 1; d < 8; d <<= 1)
                ps += __shfl_xor_sync(0xffffffffu, ps, d);
            float corr = (mold > -1e37f) ? __expf(mold - mnew) : 0.f;
            *(float4*)&Ss[sr][part * 4] = p4;
            if (part == 0) {
                ls[sr] = ls[sr] * corr + ps;
                ms[sr] = mnew;
                cr[sr] = corr;
            }
        }
        __syncthreads();

        // ---- PV accumulate ----
        {
            float corr = cr[pr];
            oA.x *= corr; oA.y *= corr; oA.z *= corr; oA.w *= corr;
            oB.x *= corr; oB.y *= corr; oB.z *= corr; oB.w *= corr;
#pragma unroll
            for (int jj = 0; jj < 32; jj++) {
                float p = Ss[pr][jj];
                float4 v0 = *(float4*)&Vs[jj][pc * 4];
                float4 v1 = *(float4*)&Vs[jj][32 + pc * 4];
                oA.x += p * v0.x; oA.y += p * v0.y; oA.z += p * v0.z; oA.w += p * v0.w;
                oB.x += p * v1.x; oB.y += p * v1.y; oB.z += p * v1.z; oB.w += p * v1.w;
            }
        }
        __syncthreads();
    }

    // ---- epilogue ----
    float invl = __frcp_rn(ls[pr]);
    int n = qb * 32 + pr;
    float* dst = g_attn + (size_t)n * DIM + h * 64;
    oA.x *= invl; oA.y *= invl; oA.z *= invl; oA.w *= invl;
    oB.x *= invl; oB.y *= invl; oB.z *= invl; oB.w *= invl;
    *(float4*)(dst + pc * 4) = oA;
    *(float4*)(dst + 32 + pc * 4) = oB;
}

// ---------------------------------------------------------------------------
extern "C" void kernel_launch(void* const* d_in, const int* in_sizes, int n_in,
                              void* d_out, int out_size) {
    const float* x_hyp    = (const float*)d_in[0];
    const float* freqs    = (const float*)d_in[1];
    const float* c_sphere = (const float*)d_in[2];
    const float* w_qkv    = (const float*)d_in[3];
    const float* b_qkv    = (const float*)d_in[4];
    const float* w_out    = (const float*)d_in[5];
    const float* b_out    = (const float*)d_in[6];
    const float* c_logits = (const float*)d_in[7];
    const float* geo      = (const float*)d_in[8];
    float* out = (float*)d_out;

    void *p_qkv = nullptr, *p_attn = nullptr, *p_scale = nullptr;
    cudaGetSymbolAddress(&p_qkv, g_qkv);
    cudaGetSymbolAddress(&p_attn, g_attn);
    cudaGetSymbolAddress(&p_scale, g_scale);

    // 1. logmap0 row scales
    rowscale_kernel<<<64, 256>>>(x_hyp, c_sphere);
    // 2. qkv = (x_hyp * scale) @ w_qkv + b_qkv   (M=512, N=1536, K=512)
    gemm_kernel<true><<<dim3(24, 8), 256>>>(x_hyp, w_qkv, b_qkv,
                                            (const float*)p_scale,
                                            (float*)p_qkv, NSEQ, 3 * DIM, DIM);
    // 3. RoPE + expmap0 + norms
    rope_expmap_kernel<<<512, 256>>>(freqs, c_logits);
    // 4. fused hyperbolic attention (GEMM-shaped)
    attn_kernel<<<dim3(16, 8), 256>>>(c_logits, geo);
    // 5. out = attn_out @ w_out + b_out   (M=N=K=512)
    gemm_kernel<false><<<dim3(8, 8), 256>>>((const float*)p_attn, w_out, b_out,
                                            nullptr, out, NSEQ, DIM, DIM);
}